// round 1
// baseline (speedup 1.0000x reference)
#include <cuda_runtime.h>
#include <math.h>

#define NB 8
#define NTOK 4096
#define NC 256
#define NH 8
#define CHD 32
#define IMG 64
#define QLD 768   // qkv row stride (3*C)

// ---------------- scratch (device globals; no allocation allowed) -------------
__device__ float g_xg[NB * NTOK * NC];           // 32 MB
__device__ float g_qkv[NB * NTOK * 3 * NC];      // 100 MB
__device__ float g_cmax[NB * NH * CHD];
__device__ float g_csum[NB * NH * CHD];
__device__ float g_kvp[4 * NB * NH * CHD * CHD]; // chunked partial kv
__device__ float g_pre[NB * NTOK * NC];          // 32 MB

// ---------------- K1: BatchNorm(eval) + Hardswish -----------------------------
__global__ __launch_bounds__(256) void k_bnhsw(const float* __restrict__ x,
                                               const float* __restrict__ gamma,
                                               const float* __restrict__ beta) {
    int i = blockIdx.x * blockDim.x + threadIdx.x;   // float4 index
    float4 v = ((const float4*)x)[i];
    int c0 = (i & 63) * 4;                           // channel of first lane elem
    const float inv = rsqrtf(1.0f + 1e-5f);
    float* f = (float*)&v;
#pragma unroll
    for (int j = 0; j < 4; j++) {
        float xb = f[j] * (gamma[c0 + j] * inv) + beta[c0 + j];
        f[j] = xb * fminf(fmaxf(xb + 3.0f, 0.0f), 6.0f) * (1.0f / 6.0f);
    }
    ((float4*)g_xg)[i] = v;
}

// ---------------- K2/K5: SGEMM  C[m,j] = sum_k A[m,k] * W[j,k] (+bias) --------
// A: [M,K] row-major, W: [Nd,K] row-major. 128x128x16 tiles, 8x8 per thread.
__global__ __launch_bounds__(256) void k_gemm_nt(const float* __restrict__ A,
                                                 const float* __restrict__ W,
                                                 float* __restrict__ C,
                                                 int M, int Nd, int K,
                                                 const float* __restrict__ bias) {
    const int BM = 128, BN = 128, BK = 16;
    __shared__ __align__(16) float As[BK][BM + 4];
    __shared__ __align__(16) float Bs[BK][BN + 4];
    int tid = threadIdx.x;
    int m0 = blockIdx.y * BM, n0 = blockIdx.x * BN;
    int rm = (tid >> 4) << 3;   // 0..120
    int rn = (tid & 15) << 3;   // 0..120

    float acc[8][8];
#pragma unroll
    for (int i = 0; i < 8; i++)
#pragma unroll
        for (int j = 0; j < 8; j++) acc[i][j] = 0.0f;

    for (int k0 = 0; k0 < K; k0 += BK) {
#pragma unroll
        for (int t = 0; t < 2; t++) {
            int i = tid + t * 256;          // 0..511 float4 slots
            int row = i >> 2;               // 0..127
            int c4 = (i & 3) << 2;          // 0,4,8,12
            float4 va = *(const float4*)&A[(size_t)(m0 + row) * K + k0 + c4];
            As[c4 + 0][row] = va.x; As[c4 + 1][row] = va.y;
            As[c4 + 2][row] = va.z; As[c4 + 3][row] = va.w;
            float4 vb = *(const float4*)&W[(size_t)(n0 + row) * K + k0 + c4];
            Bs[c4 + 0][row] = vb.x; Bs[c4 + 1][row] = vb.y;
            Bs[c4 + 2][row] = vb.z; Bs[c4 + 3][row] = vb.w;
        }
        __syncthreads();
#pragma unroll
        for (int kk = 0; kk < BK; kk++) {
            float4 a0 = *(const float4*)&As[kk][rm];
            float4 a1 = *(const float4*)&As[kk][rm + 4];
            float4 b0 = *(const float4*)&Bs[kk][rn];
            float4 b1 = *(const float4*)&Bs[kk][rn + 4];
            float a[8] = {a0.x, a0.y, a0.z, a0.w, a1.x, a1.y, a1.z, a1.w};
            float bb[8] = {b0.x, b0.y, b0.z, b0.w, b1.x, b1.y, b1.z, b1.w};
#pragma unroll
            for (int i = 0; i < 8; i++)
#pragma unroll
                for (int j = 0; j < 8; j++) acc[i][j] += a[i] * bb[j];
        }
        __syncthreads();
    }

    float bv[8];
#pragma unroll
    for (int j = 0; j < 8; j++) bv[j] = bias ? bias[n0 + rn + j] : 0.0f;
#pragma unroll
    for (int i = 0; i < 8; i++) {
        float4 o0 = make_float4(acc[i][0] + bv[0], acc[i][1] + bv[1],
                                acc[i][2] + bv[2], acc[i][3] + bv[3]);
        float4 o1 = make_float4(acc[i][4] + bv[4], acc[i][5] + bv[5],
                                acc[i][6] + bv[6], acc[i][7] + bv[7]);
        float* dst = &C[(size_t)(m0 + rm + i) * Nd + n0 + rn];
        *(float4*)dst = o0;
        *(float4*)(dst + 4) = o1;
    }
}

// ---------------- K3a: softmax stats (max, sum exp) per (b,h,ch) --------------
__global__ __launch_bounds__(1024) void k_softstats() {
    int bh = blockIdx.x;               // 0..63
    int b = bh >> 3, head = bh & 7;
    int c = threadIdx.x & 31, grp = threadIdx.x >> 5;   // 32 groups x 32 ch
    const float* kb = g_qkv + (size_t)b * NTOK * QLD + 256 + head * 32 + c;

    __shared__ float red[32][33];
    __shared__ float s_cmax[32];

    float m = -1e30f;
    for (int i = 0; i < 128; i++)
        m = fmaxf(m, kb[(size_t)(grp * 128 + i) * QLD]);
    red[grp][c] = m;
    __syncthreads();
    if (threadIdx.x < 32) {
        float mm = red[0][threadIdx.x];
#pragma unroll
        for (int g = 1; g < 32; g++) mm = fmaxf(mm, red[g][threadIdx.x]);
        s_cmax[threadIdx.x] = mm;
        g_cmax[bh * 32 + threadIdx.x] = mm;
    }
    __syncthreads();
    float cm = s_cmax[c];
    float s = 0.0f;
    for (int i = 0; i < 128; i++)
        s += __expf(kb[(size_t)(grp * 128 + i) * QLD] - cm);
    red[grp][c] = s;
    __syncthreads();
    if (threadIdx.x < 32) {
        float ss = 0.0f;
#pragma unroll
        for (int g = 0; g < 32; g++) ss += red[g][threadIdx.x];
        g_csum[bh * 32 + threadIdx.x] = ss;
    }
}

// ---------------- K3b: kv = softmax(k)^T v, chunked partials -------------------
__global__ __launch_bounds__(256) void k_kv() {
    int chunk = blockIdx.x;            // 0..3 (1024 tokens each)
    int bh = blockIdx.y;               // 0..63
    int b = bh >> 3, head = bh & 7;

    __shared__ __align__(16) float ks[128][32];
    __shared__ __align__(16) float vs[128][32];

    int tid = threadIdx.x;
    int lc = tid & 31, lr = tid >> 5;
    float cm = g_cmax[bh * 32 + lc];
    float rs = 1.0f / g_csum[bh * 32 + lc];

    const float* base = g_qkv + (size_t)(b * NTOK + chunk * 1024) * QLD + head * 32;

    int cc = tid >> 3;            // 0..31  (k-channel row)
    int cq = (tid & 7) << 2;      // 0,4,...,28 (v-channel group)
    float a0 = 0.f, a1 = 0.f, a2 = 0.f, a3 = 0.f;

    for (int t = 0; t < 8; t++) {
        const float* tb = base + (size_t)t * 128 * QLD;
#pragma unroll
        for (int r = lr; r < 128; r += 8) {
            size_t off = (size_t)r * QLD;
            ks[r][lc] = __expf(tb[off + 256 + lc] - cm) * rs;
            vs[r][lc] = tb[off + 512 + lc];
        }
        __syncthreads();
#pragma unroll 8
        for (int n = 0; n < 128; n++) {
            float kv = ks[n][cc];
            float4 vv = *(const float4*)&vs[n][cq];
            a0 += kv * vv.x; a1 += kv * vv.y; a2 += kv * vv.z; a3 += kv * vv.w;
        }
        __syncthreads();
    }
    float4 o = make_float4(a0, a1, a2, a3);
    *(float4*)&g_kvp[((size_t)chunk * 64 + bh) * 1024 + cc * 32 + cq] = o;
}

// ---------------- K4: depthwise conv + crpe + eff -> pre ----------------------
template <int KSZ>
__device__ __forceinline__ void conv_row(const float* __restrict__ qbase,
                                         const float* __restrict__ vbase,
                                         const float* __restrict__ wrow,
                                         float biasv, const float* kvcol,
                                         int b, int head, int y, int lane) {
    const int P = KSZ / 2;
    const float scale = 0.1767766952966369f;  // 32^-0.5
    for (int x = 0; x < IMG; x++) {
        int n = y * IMG + x;
        float q = qbase[(size_t)n * QLD];
        float acc = biasv;
#pragma unroll
        for (int dy = 0; dy < KSZ; dy++) {
            int yy = y + dy - P;
            if ((unsigned)yy < (unsigned)IMG) {
#pragma unroll
                for (int dx = 0; dx < KSZ; dx++) {
                    int xx = x + dx - P;
                    if ((unsigned)xx < (unsigned)IMG)
                        acc += vbase[(size_t)(yy * IMG + xx) * QLD] * wrow[dy * KSZ + dx];
                }
            }
        }
        float e = 0.0f;
#pragma unroll
        for (int kk = 0; kk < 32; kk++)
            e += __shfl_sync(0xffffffffu, q, kk) * kvcol[kk];
        g_pre[(size_t)(b * NTOK + n) * NC + head * 32 + lane] = scale * e + q * acc;
    }
}

__global__ __launch_bounds__(256) void k_conv_att(const float* __restrict__ w3,
                                                  const float* __restrict__ b3,
                                                  const float* __restrict__ w5,
                                                  const float* __restrict__ b5,
                                                  const float* __restrict__ w7,
                                                  const float* __restrict__ b7) {
    int yt = blockIdx.x;    // 0..7 (8 rows per block)
    int head = blockIdx.y;  // 0..7
    int b = blockIdx.z;     // 0..7
    int lane = threadIdx.x & 31, w = threadIdx.x >> 5;
    int bh = b * 8 + head;

    __shared__ float kv_s[1024];
    __shared__ float w_s[32 * 49];
    __shared__ float bias_s[32];

    for (int i = threadIdx.x; i < 1024; i += 256) {
        float s = 0.0f;
#pragma unroll
        for (int ch = 0; ch < 4; ch++) s += g_kvp[((size_t)ch * 64 + bh) * 1024 + i];
        kv_s[i] = s;
    }

    int ksz, chb;
    const float* wp;
    const float* bp;
    if (head < 2)      { ksz = 3; wp = w3; bp = b3; chb = head * 32; }
    else if (head < 5) { ksz = 5; wp = w5; bp = b5; chb = head * 32 - 64; }
    else               { ksz = 7; wp = w7; bp = b7; chb = head * 32 - 160; }
    int ntap = ksz * ksz;
    for (int i = threadIdx.x; i < 32 * ntap; i += 256)
        w_s[i] = wp[chb * ntap + i];
    if (threadIdx.x < 32) bias_s[threadIdx.x] = bp[chb + threadIdx.x];
    __syncthreads();

    float kvcol[32];
#pragma unroll
    for (int kk = 0; kk < 32; kk++) kvcol[kk] = kv_s[kk * 32 + lane];

    const float* qbase = g_qkv + (size_t)b * NTOK * QLD + head * 32 + lane;
    const float* vbase = qbase + 512;
    const float* wrow = w_s + lane * ntap;
    float biasv = bias_s[lane];
    int y = yt * 8 + w;

    if (head < 2)      conv_row<3>(qbase, vbase, wrow, biasv, kvcol, b, head, y, lane);
    else if (head < 5) conv_row<5>(qbase, vbase, wrow, biasv, kvcol, b, head, y, lane);
    else               conv_row<7>(qbase, vbase, wrow, biasv, kvcol, b, head, y, lane);
}

// ---------------- launch -------------------------------------------------------
extern "C" void kernel_launch(void* const* d_in, const int* in_sizes, int n_in,
                              void* d_out, int out_size) {
    const float* x      = (const float*)d_in[0];
    const float* qkv_w  = (const float*)d_in[1];
    const float* proj_w = (const float*)d_in[2];
    const float* proj_b = (const float*)d_in[3];
    const float* gamma  = (const float*)d_in[4];
    const float* beta   = (const float*)d_in[5];
    const float* w3     = (const float*)d_in[6];
    const float* b3     = (const float*)d_in[7];
    const float* w5     = (const float*)d_in[8];
    const float* b5     = (const float*)d_in[9];
    const float* w7     = (const float*)d_in[10];
    const float* b7     = (const float*)d_in[11];
    float* out = (float*)d_out;

    void *p_xg, *p_qkv, *p_pre;
    cudaGetSymbolAddress(&p_xg, g_xg);
    cudaGetSymbolAddress(&p_qkv, g_qkv);
    cudaGetSymbolAddress(&p_pre, g_pre);

    // 1. BN + hardswish
    k_bnhsw<<<(NB * NTOK * NC / 4) / 256, 256>>>(x, gamma, beta);

    // 2. qkv = xg @ qkv_w^T   [32768 x 768], K=256
    k_gemm_nt<<<dim3(QLD / 128, NB * NTOK / 128), 256>>>(
        (const float*)p_xg, qkv_w, (float*)p_qkv, NB * NTOK, QLD, NC, nullptr);

    // 3. softmax stats + kv
    k_softstats<<<64, 1024>>>();
    k_kv<<<dim3(4, 64), 256>>>();

    // 4. conv + crpe + eff -> pre
    k_conv_att<<<dim3(8, 8, 8), 256>>>(w3, b3, w5, b5, w7, b7);

    // 5. out = pre @ proj_w^T + proj_b   [32768 x 256], K=256
    k_gemm_nt<<<dim3(NC / 128, NB * NTOK / 128), 256>>>(
        (const float*)p_pre, proj_w, out, NB * NTOK, NC, NC, proj_b);
}

// round 2
// speedup vs baseline: 1.4740x; 1.4740x over previous
#include <cuda_runtime.h>
#include <math.h>

#define NB 8
#define NTOK 4096
#define NC 256
#define NH 8
#define CHD 32
#define IMG 64
#define QLD 768   // qkv row stride (3*C)

// ---------------- scratch (device globals; no allocation allowed) -------------
__device__ float g_xg[NB * NTOK * NC];           // tf32-rounded BN+hardswish
__device__ float g_qkv[NB * NTOK * 3 * NC];
__device__ float g_cmax[NB * NH * CHD];
__device__ float g_csum[NB * NH * CHD];
__device__ float g_kvp[4 * NB * NH * CHD * CHD];
__device__ float g_pre[NB * NTOK * NC];          // tf32-rounded pre-proj
__device__ float g_wq[QLD * NC];                 // tf32-rounded qkv_w
__device__ float g_wp[NC * NC];                  // tf32-rounded proj_w

__device__ __forceinline__ float tf32r(float x) {
    unsigned u;
    asm("cvt.rna.tf32.f32 %0, %1;" : "=r"(u) : "f"(x));
    return __uint_as_float(u);
}

// ---------------- K0: round weights to tf32 ------------------------------------
__global__ __launch_bounds__(256) void k_cvtw(const float* __restrict__ wq,
                                              const float* __restrict__ wp) {
    int i = blockIdx.x * 256 + threadIdx.x;
    if (i < QLD * NC) g_wq[i] = tf32r(wq[i]);
    if (i < NC * NC)  g_wp[i] = tf32r(wp[i]);
}

// ---------------- K1: BatchNorm(eval) + Hardswish (tf32-rounded out) -----------
__global__ __launch_bounds__(256) void k_bnhsw(const float* __restrict__ x,
                                               const float* __restrict__ gamma,
                                               const float* __restrict__ beta) {
    int i = blockIdx.x * blockDim.x + threadIdx.x;   // float4 index
    float4 v = ((const float4*)x)[i];
    int c0 = (i & 63) * 4;
    const float inv = rsqrtf(1.0f + 1e-5f);
    float* f = (float*)&v;
#pragma unroll
    for (int j = 0; j < 4; j++) {
        float xb = f[j] * (gamma[c0 + j] * inv) + beta[c0 + j];
        f[j] = tf32r(xb * fminf(fmaxf(xb + 3.0f, 0.0f), 6.0f) * (1.0f / 6.0f));
    }
    ((float4*)g_xg)[i] = v;
}

// ---------------- tensor-core TF32 GEMM  C[m,j] = sum_k A[m,k] W[j,k] (+bias) --
// A:[M,K], W:[Nd,K] row-major, K%32==0. 128x128x32 tiles, mma.m16n8k8.tf32.
#define BM 128
#define BN 128
#define BK 32
#define SST 36    // smem row stride (floats): 16B-aligned + conflict-free frags

__device__ __forceinline__ void cpa16(float* dst, const float* src) {
    unsigned d = (unsigned)__cvta_generic_to_shared(dst);
    asm volatile("cp.async.cg.shared.global [%0], [%1], 16;\n" :: "r"(d), "l"(src));
}
__device__ __forceinline__ void cp_commit() { asm volatile("cp.async.commit_group;\n"); }

__device__ __forceinline__ void mma8(float* c, const unsigned* a, const unsigned* b) {
    asm volatile(
        "mma.sync.aligned.m16n8k8.row.col.f32.tf32.tf32.f32 "
        "{%0,%1,%2,%3}, {%4,%5,%6,%7}, {%8,%9}, {%0,%1,%2,%3};"
        : "+f"(c[0]), "+f"(c[1]), "+f"(c[2]), "+f"(c[3])
        : "r"(a[0]), "r"(a[1]), "r"(a[2]), "r"(a[3]), "r"(b[0]), "r"(b[1]));
}

extern __shared__ float smem_g[];

__global__ __launch_bounds__(256) void k_gemm_tc(const float* __restrict__ A,
                                                 const float* __restrict__ W,
                                                 float* __restrict__ C,
                                                 int M, int Nd, int K,
                                                 const float* __restrict__ bias) {
    float* As0 = smem_g;
    float* Bs0 = smem_g + BM * SST;
    float* As1 = smem_g + 2 * BM * SST;
    float* Bs1 = smem_g + 3 * BM * SST;
    float* Asb[2] = {As0, As1};
    float* Bsb[2] = {Bs0, Bs1};

    int tid = threadIdx.x;
    int m0 = blockIdx.y * BM, n0 = blockIdx.x * BN;
    int warp = tid >> 5, lane = tid & 31;
    int g = lane >> 2, t = lane & 3;
    int wm = (warp >> 2) * 64;
    int wn = (warp & 3) * 32;

    float acc[4][4][4];
#pragma unroll
    for (int mt = 0; mt < 4; mt++)
#pragma unroll
        for (int nt = 0; nt < 4; nt++)
#pragma unroll
            for (int r = 0; r < 4; r++) acc[mt][nt][r] = 0.0f;

    const int nch = K >> 5;   // chunks of 32

    // cp.async stage issue: 1024 16B-chunks each for A and B, 4 per thread each
    auto issue = [&](int k0, float* as, float* bs) {
#pragma unroll
        for (int j = 0; j < 4; j++) {
            int ci = tid + 256 * j;
            int row = ci >> 3;
            int kc = (ci & 7) << 2;
            cpa16(as + row * SST + kc, A + (size_t)(m0 + row) * K + k0 + kc);
            cpa16(bs + row * SST + kc, W + (size_t)(n0 + row) * K + k0 + kc);
        }
    };

    issue(0, Asb[0], Bsb[0]);
    cp_commit();

    for (int c = 0; c < nch; c++) {
        if (c + 1 < nch) {
            issue((c + 1) * BK, Asb[(c + 1) & 1], Bsb[(c + 1) & 1]);
            cp_commit();
            asm volatile("cp.async.wait_group 1;\n");
        } else {
            asm volatile("cp.async.wait_group 0;\n");
        }
        __syncthreads();

        const float* as = Asb[c & 1];
        const float* bs = Bsb[c & 1];
#pragma unroll
        for (int ks = 0; ks < 4; ks++) {
            int kb = ks * 8;
            unsigned af[4][4], bf[4][2];
#pragma unroll
            for (int mt = 0; mt < 4; mt++) {
                int r = wm + mt * 16;
                af[mt][0] = __float_as_uint(as[(r + g) * SST + kb + t]);
                af[mt][1] = __float_as_uint(as[(r + g + 8) * SST + kb + t]);
                af[mt][2] = __float_as_uint(as[(r + g) * SST + kb + t + 4]);
                af[mt][3] = __float_as_uint(as[(r + g + 8) * SST + kb + t + 4]);
            }
#pragma unroll
            for (int nt = 0; nt < 4; nt++) {
                int cn = (wn + nt * 8 + g) * SST + kb;
                bf[nt][0] = __float_as_uint(bs[cn + t]);
                bf[nt][1] = __float_as_uint(bs[cn + t + 4]);
            }
#pragma unroll
            for (int mt = 0; mt < 4; mt++)
#pragma unroll
                for (int nt = 0; nt < 4; nt++)
                    mma8(acc[mt][nt], af[mt], bf[nt]);
        }
        __syncthreads();
    }

    // epilogue
#pragma unroll
    for (int mt = 0; mt < 4; mt++) {
#pragma unroll
        for (int nt = 0; nt < 4; nt++) {
            int col = n0 + wn + nt * 8 + 2 * t;
            float b0 = bias ? bias[col] : 0.0f;
            float b1 = bias ? bias[col + 1] : 0.0f;
            int row0 = m0 + wm + mt * 16 + g;
            float2 o0 = make_float2(acc[mt][nt][0] + b0, acc[mt][nt][1] + b1);
            float2 o1 = make_float2(acc[mt][nt][2] + b0, acc[mt][nt][3] + b1);
            *(float2*)&C[(size_t)row0 * Nd + col] = o0;
            *(float2*)&C[(size_t)(row0 + 8) * Nd + col] = o1;
        }
    }
}

// ---------------- K3a: softmax stats (max, sum exp) per (b,h,ch) --------------
__global__ __launch_bounds__(1024) void k_softstats() {
    int bh = blockIdx.x;
    int b = bh >> 3, head = bh & 7;
    int c = threadIdx.x & 31, grp = threadIdx.x >> 5;
    const float* kb = g_qkv + (size_t)b * NTOK * QLD + 256 + head * 32 + c;

    __shared__ float red[32][33];
    __shared__ float s_cmax[32];

    float m = -1e30f;
    for (int i = 0; i < 128; i++)
        m = fmaxf(m, kb[(size_t)(grp * 128 + i) * QLD]);
    red[grp][c] = m;
    __syncthreads();
    if (threadIdx.x < 32) {
        float mm = red[0][threadIdx.x];
#pragma unroll
        for (int gg = 1; gg < 32; gg++) mm = fmaxf(mm, red[gg][threadIdx.x]);
        s_cmax[threadIdx.x] = mm;
        g_cmax[bh * 32 + threadIdx.x] = mm;
    }
    __syncthreads();
    float cm = s_cmax[c];
    float s = 0.0f;
    for (int i = 0; i < 128; i++)
        s += __expf(kb[(size_t)(grp * 128 + i) * QLD] - cm);
    red[grp][c] = s;
    __syncthreads();
    if (threadIdx.x < 32) {
        float ss = 0.0f;
#pragma unroll
        for (int gg = 0; gg < 32; gg++) ss += red[gg][threadIdx.x];
        g_csum[bh * 32 + threadIdx.x] = ss;
    }
}

// ---------------- K3b: kv = softmax(k)^T v, chunked partials -------------------
__global__ __launch_bounds__(256) void k_kv() {
    int chunk = blockIdx.x;
    int bh = blockIdx.y;
    int b = bh >> 3, head = bh & 7;

    __shared__ __align__(16) float ks[128][32];
    __shared__ __align__(16) float vs[128][32];

    int tid = threadIdx.x;
    int lc = tid & 31, lr = tid >> 5;
    float cm = g_cmax[bh * 32 + lc];
    float rs = 1.0f / g_csum[bh * 32 + lc];

    const float* base = g_qkv + (size_t)(b * NTOK + chunk * 1024) * QLD + head * 32;

    int cc = tid >> 3;
    int cq = (tid & 7) << 2;
    float a0 = 0.f, a1 = 0.f, a2 = 0.f, a3 = 0.f;

    for (int tch = 0; tch < 8; tch++) {
        const float* tb = base + (size_t)tch * 128 * QLD;
#pragma unroll
        for (int r = lr; r < 128; r += 8) {
            size_t off = (size_t)r * QLD;
            ks[r][lc] = __expf(tb[off + 256 + lc] - cm) * rs;
            vs[r][lc] = tb[off + 512 + lc];
        }
        __syncthreads();
#pragma unroll 8
        for (int n = 0; n < 128; n++) {
            float kv = ks[n][cc];
            float4 vv = *(const float4*)&vs[n][cq];
            a0 += kv * vv.x; a1 += kv * vv.y; a2 += kv * vv.z; a3 += kv * vv.w;
        }
        __syncthreads();
    }
    float4 o = make_float4(a0, a1, a2, a3);
    *(float4*)&g_kvp[((size_t)chunk * 64 + bh) * 1024 + cc * 32 + cq] = o;
}

// ---------------- K4: depthwise conv + crpe + eff -> pre ----------------------
template <int KSZ>
__device__ __forceinline__ void conv_row(const float* __restrict__ qbase,
                                         const float* __restrict__ vbase,
                                         const float* __restrict__ wrow,
                                         float biasv, const float* kvcol,
                                         int b, int head, int y, int lane) {
    const int P = KSZ / 2;
    const float scale = 0.1767766952966369f;  // 32^-0.5
    for (int x = 0; x < IMG; x++) {
        int n = y * IMG + x;
        float q = qbase[(size_t)n * QLD];
        float acc = biasv;
#pragma unroll
        for (int dy = 0; dy < KSZ; dy++) {
            int yy = y + dy - P;
            if ((unsigned)yy < (unsigned)IMG) {
#pragma unroll
                for (int dx = 0; dx < KSZ; dx++) {
                    int xx = x + dx - P;
                    if ((unsigned)xx < (unsigned)IMG)
                        acc += vbase[(size_t)(yy * IMG + xx) * QLD] * wrow[dy * KSZ + dx];
                }
            }
        }
        float e = 0.0f;
#pragma unroll
        for (int kk = 0; kk < 32; kk++)
            e += __shfl_sync(0xffffffffu, q, kk) * kvcol[kk];
        g_pre[(size_t)(b * NTOK + n) * NC + head * 32 + lane] =
            tf32r(scale * e + q * acc);
    }
}

__global__ __launch_bounds__(256) void k_conv_att(const float* __restrict__ w3,
                                                  const float* __restrict__ b3,
                                                  const float* __restrict__ w5,
                                                  const float* __restrict__ b5,
                                                  const float* __restrict__ w7,
                                                  const float* __restrict__ b7) {
    int yt = blockIdx.x;
    int head = blockIdx.y;
    int b = blockIdx.z;
    int lane = threadIdx.x & 31, w = threadIdx.x >> 5;
    int bh = b * 8 + head;

    __shared__ float kv_s[1024];
    __shared__ float w_s[32 * 49];
    __shared__ float bias_s[32];

    for (int i = threadIdx.x; i < 1024; i += 256) {
        float s = 0.0f;
#pragma unroll
        for (int ch = 0; ch < 4; ch++) s += g_kvp[((size_t)ch * 64 + bh) * 1024 + i];
        kv_s[i] = s;
    }

    int ksz, chb;
    const float* wp;
    const float* bp;
    if (head < 2)      { ksz = 3; wp = w3; bp = b3; chb = head * 32; }
    else if (head < 5) { ksz = 5; wp = w5; bp = b5; chb = head * 32 - 64; }
    else               { ksz = 7; wp = w7; bp = b7; chb = head * 32 - 160; }
    int ntap = ksz * ksz;
    for (int i = threadIdx.x; i < 32 * ntap; i += 256)
        w_s[i] = wp[chb * ntap + i];
    if (threadIdx.x < 32) bias_s[threadIdx.x] = bp[chb + threadIdx.x];
    __syncthreads();

    float kvcol[32];
#pragma unroll
    for (int kk = 0; kk < 32; kk++) kvcol[kk] = kv_s[kk * 32 + lane];

    const float* qbase = g_qkv + (size_t)b * NTOK * QLD + head * 32 + lane;
    const float* vbase = qbase + 512;
    const float* wrow = w_s + lane * ntap;
    float biasv = bias_s[lane];
    int y = yt * 8 + w;

    if (head < 2)      conv_row<3>(qbase, vbase, wrow, biasv, kvcol, b, head, y, lane);
    else if (head < 5) conv_row<5>(qbase, vbase, wrow, biasv, kvcol, b, head, y, lane);
    else               conv_row<7>(qbase, vbase, wrow, biasv, kvcol, b, head, y, lane);
}

// ---------------- launch -------------------------------------------------------
extern "C" void kernel_launch(void* const* d_in, const int* in_sizes, int n_in,
                              void* d_out, int out_size) {
    const float* x      = (const float*)d_in[0];
    const float* qkv_w  = (const float*)d_in[1];
    const float* proj_w = (const float*)d_in[2];
    const float* proj_b = (const float*)d_in[3];
    const float* gamma  = (const float*)d_in[4];
    const float* beta   = (const float*)d_in[5];
    const float* w3     = (const float*)d_in[6];
    const float* b3     = (const float*)d_in[7];
    const float* w5     = (const float*)d_in[8];
    const float* b5     = (const float*)d_in[9];
    const float* w7     = (const float*)d_in[10];
    const float* b7     = (const float*)d_in[11];
    float* out = (float*)d_out;

    void *p_xg, *p_qkv, *p_pre, *p_wq, *p_wp;
    cudaGetSymbolAddress(&p_xg, g_xg);
    cudaGetSymbolAddress(&p_qkv, g_qkv);
    cudaGetSymbolAddress(&p_pre, g_pre);
    cudaGetSymbolAddress(&p_wq, g_wq);
    cudaGetSymbolAddress(&p_wp, g_wp);

    static int smem_set = 0;
    const int SMEM_BYTES = 4 * BM * SST * 4;   // 73728
    if (!smem_set) {
        cudaFuncSetAttribute(k_gemm_tc, cudaFuncAttributeMaxDynamicSharedMemorySize,
                             SMEM_BYTES);
        smem_set = 1;
    }

    // 0. round weights
    k_cvtw<<<(QLD * NC + 255) / 256, 256>>>(qkv_w, proj_w);

    // 1. BN + hardswish (tf32 out)
    k_bnhsw<<<(NB * NTOK * NC / 4) / 256, 256>>>(x, gamma, beta);

    // 2. qkv = xg @ qkv_w^T   [32768 x 768], K=256  (tensor cores)
    k_gemm_tc<<<dim3(QLD / BN, NB * NTOK / BM), 256, SMEM_BYTES>>>(
        (const float*)p_xg, (const float*)p_wq, (float*)p_qkv,
        NB * NTOK, QLD, NC, nullptr);

    // 3. softmax stats + kv
    k_softstats<<<64, 1024>>>();
    k_kv<<<dim3(4, 64), 256>>>();

    // 4. conv + crpe + eff -> pre (tf32 out)
    k_conv_att<<<dim3(8, 8, 8), 256>>>(w3, b3, w5, b5, w7, b7);

    // 5. out = pre @ proj_w^T + proj_b   [32768 x 256], K=256  (tensor cores)
    k_gemm_tc<<<dim3(NC / BN, NB * NTOK / BM), 256, SMEM_BYTES>>>(
        (const float*)p_pre, (const float*)p_wp, out,
        NB * NTOK, NC, NC, proj_b);
}